// round 4
// baseline (speedup 1.0000x reference)
#include <cuda_runtime.h>
#include <cuda_bf16.h>
#include <cstdint>

#define TT 2048
#define HH 4096
#define OO 4096
#define LL 32
#define RR 16

// ---------------- device scratch (no cudaMalloc allowed) ----------------
__device__ __nv_bfloat16 g_xhi[TT * HH];   // row-major [T][H]
__device__ __nv_bfloat16 g_xlo[TT * HH];
__device__ __nv_bfloat16 g_whi[OO * HH];   // row-major [O][H]
__device__ __nv_bfloat16 g_wlo[OO * HH];
__device__ int   g_cnt[LL];
__device__ int   g_off[LL];
__device__ int   g_tok[TT];
__device__ float g_shrunk[TT * RR];

// ---------------- prep: index width detect + group tokens by adapter ----------------
__global__ void prep_kernel(const int* __restrict__ w) {
    __shared__ int s_ok;
    __shared__ int s_cnt[LL];
    __shared__ int s_off[LL];
    int tid = threadIdx.x;
    if (tid == 0) s_ok = 1;
    if (tid < LL) s_cnt[tid] = 0;
    __syncthreads();
    // int64 detection: viewed as int32 pairs (lo,hi), hi must be the sign
    // extension of a valid index in [-1, LL)
    if (tid < 1024) {
        int lo = w[2 * tid], hi = w[2 * tid + 1];
        int expect = (lo < 0) ? -1 : 0;
        if (hi != expect || lo < -1 || lo >= LL) atomicExch(&s_ok, 0);
    }
    __syncthreads();
    int is64 = s_ok;
    for (int t = tid; t < TT; t += 1024) {
        int l = is64 ? w[2 * t] : w[t];
        if (l >= 0) atomicAdd(&s_cnt[l], 1);
    }
    __syncthreads();
    if (tid == 0) {
        int a = 0;
        for (int l = 0; l < LL; l++) { s_off[l] = a; a += s_cnt[l]; }
    }
    __syncthreads();
    if (tid < LL) { g_off[tid] = s_off[tid]; g_cnt[tid] = s_cnt[tid]; }
    if (tid < LL) s_cnt[tid] = 0;
    __syncthreads();
    for (int t = tid; t < TT; t += 1024) {
        int l = is64 ? w[2 * t] : w[t];
        if (l >= 0) {
            int p = atomicAdd(&s_cnt[l], 1);
            g_tok[s_off[l] + p] = t;
        }
    }
}

// ---------------- fp32 -> bf16 hi/lo split (row-major) ----------------
__global__ void __launch_bounds__(256) split_x_kernel(const float* __restrict__ x) {
    size_t i = ((size_t)blockIdx.x * 256 + threadIdx.x) * 8;
    float4 v0 = *reinterpret_cast<const float4*>(x + i);
    float4 v1 = *reinterpret_cast<const float4*>(x + i + 4);
    float f[8] = {v0.x, v0.y, v0.z, v0.w, v1.x, v1.y, v1.z, v1.w};
    __align__(16) __nv_bfloat16 h[8];
    __align__(16) __nv_bfloat16 l[8];
#pragma unroll
    for (int q = 0; q < 8; q++) {
        h[q] = __float2bfloat16(f[q]);
        l[q] = __float2bfloat16(f[q] - __bfloat162float(h[q]));
    }
    *reinterpret_cast<uint4*>(g_xhi + i) = *reinterpret_cast<uint4*>(h);
    *reinterpret_cast<uint4*>(g_xlo + i) = *reinterpret_cast<uint4*>(l);
}

__global__ void __launch_bounds__(256) split_w_kernel(const float* __restrict__ w) {
    size_t i = ((size_t)blockIdx.x * 256 + threadIdx.x) * 8;
    float4 v0 = *reinterpret_cast<const float4*>(w + i);
    float4 v1 = *reinterpret_cast<const float4*>(w + i + 4);
    float f[8] = {v0.x, v0.y, v0.z, v0.w, v1.x, v1.y, v1.z, v1.w};
    __align__(16) __nv_bfloat16 h[8];
    __align__(16) __nv_bfloat16 l[8];
#pragma unroll
    for (int q = 0; q < 8; q++) {
        h[q] = __float2bfloat16(f[q]);
        l[q] = __float2bfloat16(f[q] - __bfloat162float(h[q]));
    }
    *reinterpret_cast<uint4*>(g_whi + i) = *reinterpret_cast<uint4*>(h);
    *reinterpret_cast<uint4*>(g_wlo + i) = *reinterpret_cast<uint4*>(l);
}

// ---------------- LoRA shrink (fp32): S[t,r] = x[t,:] . A[l,r,:] ----------------
// grid = 64: blockIdx.x = l + 32*rblk ; block handles 8 r-values, A fp32 in smem
__global__ void __launch_bounds__(256) shrink_kernel(const float* __restrict__ x,
                                                     const float* __restrict__ lora_a) {
    extern __shared__ float As[];   // 8 * 4096 fp32 = 128 KB
    int l  = blockIdx.x & 31;
    int rb = blockIdx.x >> 5;
    int tid = threadIdx.x;
    const float* Ag = lora_a + ((size_t)l * RR + rb * 8) * HH;
    for (int i = tid; i < 8 * HH / 4; i += 256) {
        *reinterpret_cast<float4*>(As + (size_t)i * 4) =
            *reinterpret_cast<const float4*>(Ag + (size_t)i * 4);
    }
    __syncthreads();
    int cnt = g_cnt[l], off = g_off[l];
    int wrp = tid >> 5, lane = tid & 31;           // wrp = local r (8 warps)
    const float* Ar = As + wrp * HH;
    for (int it = 0; it < cnt; it++) {
        int t = g_tok[off + it];
        const float* xr = x + (size_t)t * HH;
        float acc = 0.0f;
#pragma unroll 4
        for (int k = lane * 4; k < HH; k += 128) {
            float4 xv = *reinterpret_cast<const float4*>(xr + k);
            float4 av = *reinterpret_cast<const float4*>(Ar + k);
            acc += xv.x * av.x + xv.y * av.y + xv.z * av.z + xv.w * av.w;
        }
#pragma unroll
        for (int o = 16; o; o >>= 1) acc += __shfl_xor_sync(0xFFFFFFFFu, acc, o);
        if (lane == 0) g_shrunk[t * RR + rb * 8 + wrp] = acc;
    }
}

// ---------------- LoRA expand: out[t,o] += sum_r S[t,r]*B[l,o,r] ----------------
__global__ void __launch_bounds__(256) expand_kernel(const float* __restrict__ lora_b,
                                                     float* __restrict__ out) {
    __shared__ float Bs[512 * 17];
    int l  = blockIdx.x & 31;
    int oc = blockIdx.x >> 5;
    int o0 = oc * 512;
    int tid = threadIdx.x;
    const float* Bg = lora_b + ((size_t)l * OO + o0) * RR;
    for (int i = tid; i < 512 * RR; i += 256) {
        int o = i >> 4, r = i & 15;
        Bs[o * 17 + r] = Bg[i];
    }
    __syncthreads();
    int cnt = g_cnt[l], off = g_off[l];
    for (int it = 0; it < cnt; it++) {
        int t = g_tok[off + it];
        const float* sv = g_shrunk + t * RR;
        float s[RR];
#pragma unroll
        for (int r = 0; r < RR; r++) s[r] = __ldg(sv + r);
#pragma unroll
        for (int u = 0; u < 2; u++) {
            int o = tid + u * 256;
            float acc = 0.0f;
#pragma unroll
            for (int r = 0; r < RR; r++) acc += Bs[o * 17 + r] * s[r];
            out[(size_t)t * OO + o0 + o] += acc;
        }
    }
}

// ---------------- main GEMM: mma.sync bf16, bf16x3 via K-concat ----------------
// A' = [x_hi | x_lo | x_hi], B' = [w_hi | w_hi | w_lo]  -> K_eff = 12288
// CTA tile 128x128, BK=64, 4-stage cp.async pipeline, SW128 smem + ldmatrix.
#define BK       64
#define NITER    (3 * HH / BK)        /* 192 */
#define STAGE_B  32768                /* A 16K + B 16K */
#define NSTAGE   4
#define GEMM_SMEM (NSTAGE * STAGE_B)  /* 131072 */

__device__ __forceinline__ uint32_t sw128(uint32_t off) {
    return off ^ ((off >> 3) & 0x70);
}

__device__ __forceinline__ void ldsm_x4(uint32_t* r, uint32_t addr) {
    asm volatile("ldmatrix.sync.aligned.m8n8.x4.shared.b16 {%0,%1,%2,%3}, [%4];"
                 : "=r"(r[0]), "=r"(r[1]), "=r"(r[2]), "=r"(r[3]) : "r"(addr));
}
__device__ __forceinline__ void mma_bf16(float* c, const uint32_t* a, uint32_t b0, uint32_t b1) {
    asm volatile(
        "mma.sync.aligned.m16n8k16.row.col.f32.bf16.bf16.f32 "
        "{%0,%1,%2,%3}, {%4,%5,%6,%7}, {%8,%9}, {%0,%1,%2,%3};"
        : "+f"(c[0]), "+f"(c[1]), "+f"(c[2]), "+f"(c[3])
        : "r"(a[0]), "r"(a[1]), "r"(a[2]), "r"(a[3]), "r"(b0), "r"(b1));
}
__device__ __forceinline__ void cp16(uint32_t dst, const void* src) {
    asm volatile("cp.async.cg.shared.global [%0], [%1], 16;" :: "r"(dst),
                 "l"((unsigned long long)__cvta_generic_to_global((void*)src)));
}
__device__ __forceinline__ uint32_t smem_u32(const void* p) {
    uint32_t a;
    asm("{ .reg .u64 t; cvta.to.shared.u64 t, %1; cvt.u32.u64 %0, t; }" : "=r"(a) : "l"(p));
    return a;
}

__device__ __forceinline__ void stage_load(uint32_t sbase, int iter, int mtile, int ntile, int tid) {
    int kv  = iter * BK;
    int seg = kv >> 12;          // 0,1,2
    int koff = kv & 4095;
    const __nv_bfloat16* gA = (seg == 1) ? g_xlo : g_xhi;
    const __nv_bfloat16* gB = (seg == 2) ? g_wlo : g_whi;
    int row  = tid & 127;
    bool isB = tid >= 128;
    const __nv_bfloat16* src = isB
        ? gB + (size_t)(ntile * 128 + row) * HH + koff
        : gA + (size_t)(mtile * 128 + row) * HH + koff;
    uint32_t dstbase = sbase + (isB ? 16384 : 0);
#pragma unroll
    for (int c = 0; c < 8; c++) {
        uint32_t off = row * 128 + c * 16;
        cp16(dstbase + sw128(off), src + c * 8);
    }
}

__global__ void __launch_bounds__(256, 1) gemm_kernel(const float* __restrict__ bias,
                                                      float* __restrict__ out) {
    extern __shared__ char smem[];
    uint32_t sb = smem_u32(smem);
    int tid = threadIdx.x;
    int lane = tid & 31, wid = tid >> 5;
    int wm = wid & 1, wn = wid >> 1;          // warp grid 2 (M) x 4 (N)
    int ntile = blockIdx.x;                   // 32
    int mtile = blockIdx.y;                   // 16

    float acc[4][4][4];
#pragma unroll
    for (int i = 0; i < 4; i++)
#pragma unroll
        for (int j = 0; j < 4; j++)
#pragma unroll
            for (int q = 0; q < 4; q++) acc[i][j][q] = 0.0f;

    // prologue: 3 stages in flight
#pragma unroll
    for (int s = 0; s < NSTAGE - 1; s++) {
        stage_load(sb + s * STAGE_B, s, mtile, ntile, tid);
        asm volatile("cp.async.commit_group;" ::: "memory");
    }

    int arow = (lane & 15);
    int achk = (lane >> 4) * 16;

    for (int it = 0; it < NITER; it++) {
        asm volatile("cp.async.wait_group %0;" :: "n"(NSTAGE - 2) : "memory");
        __syncthreads();
        // issue next stage (overwrites the buffer consumed 1 iter ago)
        if (it + NSTAGE - 1 < NITER) {
            stage_load(sb + ((it + NSTAGE - 1) & (NSTAGE - 1)) * STAGE_B,
                       it + NSTAGE - 1, mtile, ntile, tid);
        }
        asm volatile("cp.async.commit_group;" ::: "memory");

        uint32_t Ab = sb + (it & (NSTAGE - 1)) * STAGE_B;
        uint32_t Bb = Ab + 16384;
#pragma unroll
        for (int ks = 0; ks < 4; ks++) {
            uint32_t a[4][4];
#pragma unroll
            for (int i = 0; i < 4; i++) {
                int row = wm * 64 + i * 16 + arow;
                uint32_t off = row * 128 + ks * 32 + achk;
                ldsm_x4(a[i], Ab + sw128(off));
            }
            uint32_t b[2][4];
#pragma unroll
            for (int jj = 0; jj < 2; jj++) {
                int row = wn * 32 + jj * 16 + arow;
                uint32_t off = row * 128 + ks * 32 + achk;
                ldsm_x4(b[jj], Bb + sw128(off));   // non-trans: smem holds [n][k], pairs are k-pairs
            }
#pragma unroll
            for (int i = 0; i < 4; i++)
#pragma unroll
                for (int j = 0; j < 4; j++) {
                    int jj = j >> 1, p = j & 1;
                    mma_bf16(acc[i][j], a[i], b[jj][p], b[jj][p + 2]);
                }
        }
        __syncthreads();
    }

    // epilogue: add bias, store fp32
#pragma unroll
    for (int i = 0; i < 4; i++) {
#pragma unroll
        for (int j = 0; j < 4; j++) {
            int m = mtile * 128 + wm * 64 + i * 16 + (lane >> 2);
            int n = ntile * 128 + wn * 32 + j * 8 + (lane & 3) * 2;
            float2 bv = *reinterpret_cast<const float2*>(bias + n);
            float2 o0, o1;
            o0.x = acc[i][j][0] + bv.x;
            o0.y = acc[i][j][1] + bv.y;
            o1.x = acc[i][j][2] + bv.x;
            o1.y = acc[i][j][3] + bv.y;
            *reinterpret_cast<float2*>(out + (size_t)m * OO + n) = o0;
            *reinterpret_cast<float2*>(out + (size_t)(m + 8) * OO + n) = o1;
        }
    }
}

// stub symbol
__global__ void ColumnParallelLinearWithLoRA_893353198245_kernel() {}

// ---------------- launch ----------------
extern "C" void kernel_launch(void* const* d_in, const int* in_sizes, int n_in,
                              void* d_out, int out_size) {
    const float* x    = (const float*)d_in[0];
    const float* w    = (const float*)d_in[1];
    const float* bias = (const float*)d_in[2];
    const float* la   = (const float*)d_in[3];
    const float* lb   = (const float*)d_in[4];
    const int*   idx  = (const int*)d_in[5];
    float* out = (float*)d_out;

    cudaFuncSetAttribute(gemm_kernel, cudaFuncAttributeMaxDynamicSharedMemorySize, GEMM_SMEM);
    cudaFuncSetAttribute(shrink_kernel, cudaFuncAttributeMaxDynamicSharedMemorySize, 131072);

    prep_kernel<<<1, 1024>>>(idx);
    split_x_kernel<<<(TT * HH / 8) / 256, 256>>>(x);
    split_w_kernel<<<(OO * HH / 8) / 256, 256>>>(w);
    shrink_kernel<<<2 * LL, 256, 131072>>>(x, la);
    gemm_kernel<<<dim3(32, 16), 256, GEMM_SMEM>>>(bias, out);
    expand_kernel<<<LL * 8, 256>>>(lb, out);
}

// round 5
// speedup vs baseline: 1.3125x; 1.3125x over previous
#include <cuda_runtime.h>
#include <cuda_bf16.h>
#include <cstdint>

#define TT 2048
#define HH 4096
#define OO 4096
#define LL 32
#define RR 16

// ---------------- device scratch (no cudaMalloc allowed) ----------------
__device__ __nv_bfloat16 g_xhi[TT * HH];   // row-major [T][H]
__device__ __nv_bfloat16 g_xlo[TT * HH];
__device__ __nv_bfloat16 g_whi[OO * HH];   // row-major [O][H]
__device__ __nv_bfloat16 g_wlo[OO * HH];
__device__ int   g_cnt[LL];
__device__ int   g_off[LL];
__device__ int   g_tok[TT];
__device__ float g_shrunk[TT * RR];

// ---------------- prep: zero shrunk, index width detect, group tokens ----------------
__global__ void prep_kernel(const int* __restrict__ w) {
    __shared__ int s_ok;
    __shared__ int s_cnt[LL];
    __shared__ int s_off[LL];
    int tid = threadIdx.x;
    // zero the shrink accumulator (shrink uses atomicAdd)
    for (int i = tid; i < TT * RR; i += 1024) g_shrunk[i] = 0.0f;
    if (tid == 0) s_ok = 1;
    if (tid < LL) s_cnt[tid] = 0;
    __syncthreads();
    // int64 detection: viewed as int32 pairs (lo,hi), hi must be the sign
    // extension of a valid index in [-1, LL)
    if (tid < 1024) {
        int lo = w[2 * tid], hi = w[2 * tid + 1];
        int expect = (lo < 0) ? -1 : 0;
        if (hi != expect || lo < -1 || lo >= LL) atomicExch(&s_ok, 0);
    }
    __syncthreads();
    int is64 = s_ok;
    for (int t = tid; t < TT; t += 1024) {
        int l = is64 ? w[2 * t] : w[t];
        if (l >= 0) atomicAdd(&s_cnt[l], 1);
    }
    __syncthreads();
    if (tid == 0) {
        int a = 0;
        for (int l = 0; l < LL; l++) { s_off[l] = a; a += s_cnt[l]; }
    }
    __syncthreads();
    if (tid < LL) { g_off[tid] = s_off[tid]; g_cnt[tid] = s_cnt[tid]; }
    if (tid < LL) s_cnt[tid] = 0;
    __syncthreads();
    for (int t = tid; t < TT; t += 1024) {
        int l = is64 ? w[2 * t] : w[t];
        if (l >= 0) {
            int p = atomicAdd(&s_cnt[l], 1);
            g_tok[s_off[l] + p] = t;
        }
    }
}

// ---------------- fp32 -> bf16 hi/lo split (row-major) ----------------
__global__ void __launch_bounds__(256) split_x_kernel(const float* __restrict__ x) {
    size_t i = ((size_t)blockIdx.x * 256 + threadIdx.x) * 8;
    float4 v0 = *reinterpret_cast<const float4*>(x + i);
    float4 v1 = *reinterpret_cast<const float4*>(x + i + 4);
    float f[8] = {v0.x, v0.y, v0.z, v0.w, v1.x, v1.y, v1.z, v1.w};
    __align__(16) __nv_bfloat16 h[8];
    __align__(16) __nv_bfloat16 l[8];
#pragma unroll
    for (int q = 0; q < 8; q++) {
        h[q] = __float2bfloat16(f[q]);
        l[q] = __float2bfloat16(f[q] - __bfloat162float(h[q]));
    }
    *reinterpret_cast<uint4*>(g_xhi + i) = *reinterpret_cast<uint4*>(h);
    *reinterpret_cast<uint4*>(g_xlo + i) = *reinterpret_cast<uint4*>(l);
}

__global__ void __launch_bounds__(256) split_w_kernel(const float* __restrict__ w) {
    size_t i = ((size_t)blockIdx.x * 256 + threadIdx.x) * 8;
    float4 v0 = *reinterpret_cast<const float4*>(w + i);
    float4 v1 = *reinterpret_cast<const float4*>(w + i + 4);
    float f[8] = {v0.x, v0.y, v0.z, v0.w, v1.x, v1.y, v1.z, v1.w};
    __align__(16) __nv_bfloat16 h[8];
    __align__(16) __nv_bfloat16 l[8];
#pragma unroll
    for (int q = 0; q < 8; q++) {
        h[q] = __float2bfloat16(f[q]);
        l[q] = __float2bfloat16(f[q] - __bfloat162float(h[q]));
    }
    *reinterpret_cast<uint4*>(g_whi + i) = *reinterpret_cast<uint4*>(h);
    *reinterpret_cast<uint4*>(g_wlo + i) = *reinterpret_cast<uint4*>(l);
}

// ---------------- LoRA shrink (fp32): S[t,r] += x[t,chunk] . A[l,r,chunk] ----------------
// grid = 256: blockIdx = l + 32*chunk; 16 warps (one per r); H split into 8 chunks of 512
#define SCH 512
__global__ void __launch_bounds__(512) shrink_kernel(const float* __restrict__ x,
                                                     const float* __restrict__ lora_a) {
    __shared__ float As[RR * SCH];   // 32 KB
    int l  = blockIdx.x & 31;
    int ch = blockIdx.x >> 5;
    int c0 = ch * SCH;
    int tid = threadIdx.x;
    const float* Ag = lora_a + (size_t)l * RR * HH + c0;
    for (int i = tid; i < RR * SCH / 4; i += 512) {
        int r = i >> 7;            // 512/4 = 128 vec4 per r
        int c = (i & 127) * 4;
        *reinterpret_cast<float4*>(As + r * SCH + c) =
            *reinterpret_cast<const float4*>(Ag + (size_t)r * HH + c);
    }
    __syncthreads();
    int cnt = g_cnt[l], off = g_off[l];
    int r = tid >> 5, lane = tid & 31;
    const float* Ar = As + r * SCH;
    for (int it = 0; it < cnt; it++) {
        int t = g_tok[off + it];
        const float* xr = x + (size_t)t * HH + c0;
        float acc = 0.0f;
#pragma unroll
        for (int j = 0; j < SCH / 32; j++)
            acc += xr[lane + 32 * j] * Ar[lane + 32 * j];
#pragma unroll
        for (int o = 16; o; o >>= 1) acc += __shfl_xor_sync(0xFFFFFFFFu, acc, o);
        if (lane == 0) atomicAdd(&g_shrunk[t * RR + r], acc);
    }
}

// ---------------- LoRA expand: out[t,o] += sum_r S[t,r]*B[l,o,r] ----------------
__global__ void __launch_bounds__(256) expand_kernel(const float* __restrict__ lora_b,
                                                     float* __restrict__ out) {
    __shared__ float Bs[512 * 17];
    int l  = blockIdx.x & 31;
    int oc = blockIdx.x >> 5;
    int o0 = oc * 512;
    int tid = threadIdx.x;
    const float* Bg = lora_b + ((size_t)l * OO + o0) * RR;
    for (int i = tid; i < 512 * RR; i += 256) {
        int o = i >> 4, r = i & 15;
        Bs[o * 17 + r] = Bg[i];
    }
    __syncthreads();
    int cnt = g_cnt[l], off = g_off[l];
    for (int it = 0; it < cnt; it++) {
        int t = g_tok[off + it];
        const float* sv = g_shrunk + t * RR;
        float s[RR];
#pragma unroll
        for (int r = 0; r < RR; r++) s[r] = __ldg(sv + r);
#pragma unroll
        for (int u = 0; u < 2; u++) {
            int o = tid + u * 256;
            float acc = 0.0f;
#pragma unroll
            for (int r = 0; r < RR; r++) acc += Bs[o * 17 + r] * s[r];
            out[(size_t)t * OO + o0 + o] += acc;
        }
    }
}

// ---------------- main GEMM: mma.sync bf16, bf16x3 via K-concat ----------------
// A' = [x_hi | x_lo | x_hi], B' = [w_hi | w_hi | w_lo]  -> K_eff = 12288
// CTA tile 128x128, BK=64, 3-stage cp.async pipeline (96 KB -> 2 CTAs/SM),
// SW128 smem + ldmatrix, single barrier per iteration.
#define BK       64
#define NITER    (3 * HH / BK)        /* 192 */
#define STAGE_B  32768                /* A 16K + B 16K */
#define NSTAGE   3
#define GEMM_SMEM (NSTAGE * STAGE_B)  /* 98304 */

__device__ __forceinline__ uint32_t sw128(uint32_t off) {
    return off ^ ((off >> 3) & 0x70);
}

__device__ __forceinline__ void ldsm_x4(uint32_t* r, uint32_t addr) {
    asm volatile("ldmatrix.sync.aligned.m8n8.x4.shared.b16 {%0,%1,%2,%3}, [%4];"
                 : "=r"(r[0]), "=r"(r[1]), "=r"(r[2]), "=r"(r[3]) : "r"(addr));
}
__device__ __forceinline__ void mma_bf16(float* c, const uint32_t* a, uint32_t b0, uint32_t b1) {
    asm volatile(
        "mma.sync.aligned.m16n8k16.row.col.f32.bf16.bf16.f32 "
        "{%0,%1,%2,%3}, {%4,%5,%6,%7}, {%8,%9}, {%0,%1,%2,%3};"
        : "+f"(c[0]), "+f"(c[1]), "+f"(c[2]), "+f"(c[3])
        : "r"(a[0]), "r"(a[1]), "r"(a[2]), "r"(a[3]), "r"(b0), "r"(b1));
}
__device__ __forceinline__ void cp16(uint32_t dst, const void* src) {
    asm volatile("cp.async.cg.shared.global [%0], [%1], 16;" :: "r"(dst),
                 "l"((unsigned long long)__cvta_generic_to_global((void*)src)));
}
__device__ __forceinline__ uint32_t smem_u32(const void* p) {
    uint32_t a;
    asm("{ .reg .u64 t; cvta.to.shared.u64 t, %1; cvt.u32.u64 %0, t; }" : "=r"(a) : "l"(p));
    return a;
}

__device__ __forceinline__ void stage_load(uint32_t sbase, int iter, int mtile, int ntile, int tid) {
    int kv  = iter * BK;
    int seg = kv >> 12;          // 0,1,2
    int koff = kv & 4095;
    const __nv_bfloat16* gA = (seg == 1) ? g_xlo : g_xhi;
    const __nv_bfloat16* gB = (seg == 2) ? g_wlo : g_whi;
    int row  = tid & 127;
    bool isB = tid >= 128;
    const __nv_bfloat16* src = isB
        ? gB + (size_t)(ntile * 128 + row) * HH + koff
        : gA + (size_t)(mtile * 128 + row) * HH + koff;
    uint32_t dstbase = sbase + (isB ? 16384 : 0);
#pragma unroll
    for (int c = 0; c < 8; c++) {
        uint32_t off = row * 128 + c * 16;
        cp16(dstbase + sw128(off), src + c * 8);
    }
}

__global__ void __launch_bounds__(256, 2) gemm_kernel(const float* __restrict__ bias,
                                                      float* __restrict__ out) {
    extern __shared__ char smem[];
    uint32_t sb = smem_u32(smem);
    int tid = threadIdx.x;
    int lane = tid & 31, wid = tid >> 5;
    int wm = wid & 1, wn = wid >> 1;          // warp grid 2 (M) x 4 (N)
    int ntile = blockIdx.x;                   // 32
    int mtile = blockIdx.y;                   // 16

    float acc[4][4][4];
#pragma unroll
    for (int i = 0; i < 4; i++)
#pragma unroll
        for (int j = 0; j < 4; j++)
#pragma unroll
            for (int q = 0; q < 4; q++) acc[i][j][q] = 0.0f;

    // prologue: 2 stages in flight
#pragma unroll
    for (int s = 0; s < NSTAGE - 1; s++) {
        stage_load(sb + s * STAGE_B, s, mtile, ntile, tid);
        asm volatile("cp.async.commit_group;" ::: "memory");
    }

    int arow = (lane & 15);
    int achk = (lane >> 4) * 16;

    int cur = 0, wrt = NSTAGE - 1;
    for (int it = 0; it < NITER; it++) {
        asm volatile("cp.async.wait_group %0;" :: "n"(NSTAGE - 2) : "memory");
        __syncthreads();
        // issue stage it+NSTAGE-1 into the buffer consumed in iteration it-1
        if (it + NSTAGE - 1 < NITER) {
            stage_load(sb + wrt * STAGE_B, it + NSTAGE - 1, mtile, ntile, tid);
        }
        asm volatile("cp.async.commit_group;" ::: "memory");

        uint32_t Ab = sb + cur * STAGE_B;
        uint32_t Bb = Ab + 16384;
#pragma unroll
        for (int ks = 0; ks < 4; ks++) {
            uint32_t a[4][4];
#pragma unroll
            for (int i = 0; i < 4; i++) {
                int row = wm * 64 + i * 16 + arow;
                uint32_t off = row * 128 + ks * 32 + achk;
                ldsm_x4(a[i], Ab + sw128(off));
            }
            uint32_t b[2][4];
#pragma unroll
            for (int jj = 0; jj < 2; jj++) {
                int row = wn * 32 + jj * 16 + arow;
                uint32_t off = row * 128 + ks * 32 + achk;
                ldsm_x4(b[jj], Bb + sw128(off));   // smem holds [n][k]: pairs are k-pairs
            }
#pragma unroll
            for (int i = 0; i < 4; i++)
#pragma unroll
                for (int j = 0; j < 4; j++) {
                    int jj = j >> 1, p = j & 1;
                    mma_bf16(acc[i][j], a[i], b[jj][p], b[jj][p + 2]);
                }
        }
        cur = (cur + 1 < NSTAGE) ? cur + 1 : 0;
        wrt = (wrt + 1 < NSTAGE) ? wrt + 1 : 0;
    }

    // epilogue: add bias, store fp32
#pragma unroll
    for (int i = 0; i < 4; i++) {
#pragma unroll
        for (int j = 0; j < 4; j++) {
            int m = mtile * 128 + wm * 64 + i * 16 + (lane >> 2);
            int n = ntile * 128 + wn * 32 + j * 8 + (lane & 3) * 2;
            float2 bv = *reinterpret_cast<const float2*>(bias + n);
            float2 o0, o1;
            o0.x = acc[i][j][0] + bv.x;
            o0.y = acc[i][j][1] + bv.y;
            o1.x = acc[i][j][2] + bv.x;
            o1.y = acc[i][j][3] + bv.y;
            *reinterpret_cast<float2*>(out + (size_t)m * OO + n) = o0;
            *reinterpret_cast<float2*>(out + (size_t)(m + 8) * OO + n) = o1;
        }
    }
}

// stub symbol
__global__ void ColumnParallelLinearWithLoRA_893353198245_kernel() {}

// ---------------- launch ----------------
extern "C" void kernel_launch(void* const* d_in, const int* in_sizes, int n_in,
                              void* d_out, int out_size) {
    const float* x    = (const float*)d_in[0];
    const float* w    = (const float*)d_in[1];
    const float* bias = (const float*)d_in[2];
    const float* la   = (const float*)d_in[3];
    const float* lb   = (const float*)d_in[4];
    const int*   idx  = (const int*)d_in[5];
    float* out = (float*)d_out;

    cudaFuncSetAttribute(gemm_kernel, cudaFuncAttributeMaxDynamicSharedMemorySize, GEMM_SMEM);

    prep_kernel<<<1, 1024>>>(idx);
    split_x_kernel<<<(TT * HH / 8) / 256, 256>>>(x);
    split_w_kernel<<<(OO * HH / 8) / 256, 256>>>(w);
    shrink_kernel<<<8 * LL, 512>>>(x, la);
    gemm_kernel<<<dim3(32, 16), 256, GEMM_SMEM>>>(bias, out);
    expand_kernel<<<LL * 8, 256>>>(lb, out);
}

// round 6
// speedup vs baseline: 1.6194x; 1.2338x over previous
#include <cuda_runtime.h>
#include <cuda_bf16.h>
#include <cstdint>

#define TT 2048
#define HH 4096
#define OO 4096
#define LL 32
#define RR 16

// ---------------- device scratch (no cudaMalloc allowed) ----------------
__device__ __nv_bfloat16 g_xhi[TT * HH];   // row-major [T][H]
__device__ __nv_bfloat16 g_xlo[TT * HH];
__device__ __nv_bfloat16 g_whi[OO * HH];   // row-major [O][H]
__device__ __nv_bfloat16 g_wlo[OO * HH];
__device__ int   g_cnt[LL];
__device__ int   g_off[LL];
__device__ int   g_tok[TT];
__device__ float g_shrunk[TT * RR];

// ---------------- prep: zero shrunk, index width detect, group tokens ----------------
__global__ void prep_kernel(const int* __restrict__ w) {
    __shared__ int s_ok;
    __shared__ int s_cnt[LL];
    __shared__ int s_off[LL];
    int tid = threadIdx.x;
    for (int i = tid; i < TT * RR; i += 1024) g_shrunk[i] = 0.0f;
    if (tid == 0) s_ok = 1;
    if (tid < LL) s_cnt[tid] = 0;
    __syncthreads();
    // int64 detection: viewed as int32 pairs (lo,hi), hi must be the sign
    // extension of a valid index in [-1, LL)
    if (tid < 1024) {
        int lo = w[2 * tid], hi = w[2 * tid + 1];
        int expect = (lo < 0) ? -1 : 0;
        if (hi != expect || lo < -1 || lo >= LL) atomicExch(&s_ok, 0);
    }
    __syncthreads();
    int is64 = s_ok;
    for (int t = tid; t < TT; t += 1024) {
        int l = is64 ? w[2 * t] : w[t];
        if (l >= 0) atomicAdd(&s_cnt[l], 1);
    }
    __syncthreads();
    if (tid == 0) {
        int a = 0;
        for (int l = 0; l < LL; l++) { s_off[l] = a; a += s_cnt[l]; }
    }
    __syncthreads();
    if (tid < LL) { g_off[tid] = s_off[tid]; g_cnt[tid] = s_cnt[tid]; }
    if (tid < LL) s_cnt[tid] = 0;
    __syncthreads();
    for (int t = tid; t < TT; t += 1024) {
        int l = is64 ? w[2 * t] : w[t];
        if (l >= 0) {
            int p = atomicAdd(&s_cnt[l], 1);
            g_tok[s_off[l] + p] = t;
        }
    }
}

// ---------------- fp32 -> bf16 hi/lo split (row-major) ----------------
__global__ void __launch_bounds__(256) split_x_kernel(const float* __restrict__ x) {
    size_t i = ((size_t)blockIdx.x * 256 + threadIdx.x) * 8;
    float4 v0 = *reinterpret_cast<const float4*>(x + i);
    float4 v1 = *reinterpret_cast<const float4*>(x + i + 4);
    float f[8] = {v0.x, v0.y, v0.z, v0.w, v1.x, v1.y, v1.z, v1.w};
    __align__(16) __nv_bfloat16 h[8];
    __align__(16) __nv_bfloat16 l[8];
#pragma unroll
    for (int q = 0; q < 8; q++) {
        h[q] = __float2bfloat16(f[q]);
        l[q] = __float2bfloat16(f[q] - __bfloat162float(h[q]));
    }
    *reinterpret_cast<uint4*>(g_xhi + i) = *reinterpret_cast<uint4*>(h);
    *reinterpret_cast<uint4*>(g_xlo + i) = *reinterpret_cast<uint4*>(l);
}

__global__ void __launch_bounds__(256) split_w_kernel(const float* __restrict__ w) {
    size_t i = ((size_t)blockIdx.x * 256 + threadIdx.x) * 8;
    float4 v0 = *reinterpret_cast<const float4*>(w + i);
    float4 v1 = *reinterpret_cast<const float4*>(w + i + 4);
    float f[8] = {v0.x, v0.y, v0.z, v0.w, v1.x, v1.y, v1.z, v1.w};
    __align__(16) __nv_bfloat16 h[8];
    __align__(16) __nv_bfloat16 l[8];
#pragma unroll
    for (int q = 0; q < 8; q++) {
        h[q] = __float2bfloat16(f[q]);
        l[q] = __float2bfloat16(f[q] - __bfloat162float(h[q]));
    }
    *reinterpret_cast<uint4*>(g_whi + i) = *reinterpret_cast<uint4*>(h);
    *reinterpret_cast<uint4*>(g_wlo + i) = *reinterpret_cast<uint4*>(l);
}

// ---------------- LoRA shrink (fp32): warp-per-token ----------------
// grid = 256: blockIdx = l + 32*chunk; 16 warps, warp w handles tokens w, w+16, ...
// Each warp computes all 16 ranks for its token from registers.
#define SCH 512
__global__ void __launch_bounds__(512) shrink_kernel(const float* __restrict__ x,
                                                     const float* __restrict__ lora_a) {
    __shared__ float As[RR * SCH];   // 32 KB
    int l  = blockIdx.x & 31;
    int ch = blockIdx.x >> 5;
    int c0 = ch * SCH;
    int tid = threadIdx.x;
    const float* Ag = lora_a + (size_t)l * RR * HH + c0;
    for (int i = tid; i < RR * SCH / 4; i += 512) {
        int r = i >> 7;            // 128 vec4 per r
        int c = (i & 127) * 4;
        *reinterpret_cast<float4*>(As + r * SCH + c) =
            *reinterpret_cast<const float4*>(Ag + (size_t)r * HH + c);
    }
    __syncthreads();
    int cnt = g_cnt[l], off = g_off[l];
    int wrp = tid >> 5, lane = tid & 31;
    for (int it = wrp; it < cnt; it += 16) {
        int t = g_tok[off + it];
        const float* xr = x + (size_t)t * HH + c0;
        float xv[16];
#pragma unroll
        for (int j = 0; j < 16; j++) xv[j] = xr[lane + 32 * j];
        float mine = 0.0f;
#pragma unroll
        for (int r = 0; r < RR; r++) {
            float a = 0.0f;
            const float* Ar = As + r * SCH;
#pragma unroll
            for (int j = 0; j < 16; j++) a += xv[j] * Ar[lane + 32 * j];
#pragma unroll
            for (int o = 16; o; o >>= 1) a += __shfl_xor_sync(0xFFFFFFFFu, a, o);
            if (lane == r) mine = a;
        }
        if (lane < RR) atomicAdd(&g_shrunk[t * RR + lane], mine);
    }
}

// ---------------- LoRA expand: out[t,o] += sum_r S[t,r]*B[l,o,r] ----------------
__global__ void __launch_bounds__(256) expand_kernel(const float* __restrict__ lora_b,
                                                     float* __restrict__ out) {
    __shared__ float Bs[512 * 17];
    int l  = blockIdx.x & 31;
    int oc = blockIdx.x >> 5;
    int o0 = oc * 512;
    int tid = threadIdx.x;
    const float* Bg = lora_b + ((size_t)l * OO + o0) * RR;
    for (int i = tid; i < 512 * RR; i += 256) {
        int o = i >> 4, r = i & 15;
        Bs[o * 17 + r] = Bg[i];
    }
    __syncthreads();
    int cnt = g_cnt[l], off = g_off[l];
    for (int it = 0; it < cnt; it++) {
        int t = g_tok[off + it];
        const float* sv = g_shrunk + t * RR;
        float s[RR];
#pragma unroll
        for (int r = 0; r < RR; r++) s[r] = __ldg(sv + r);
#pragma unroll
        for (int u = 0; u < 2; u++) {
            int o = tid + u * 256;
            float acc = 0.0f;
#pragma unroll
            for (int r = 0; r < RR; r++) acc += Bs[o * 17 + r] * s[r];
            out[(size_t)t * OO + o0 + o] += acc;
        }
    }
}

// ---------------- main GEMM: mma.sync bf16, fused 3-pass bf16x3 ----------------
// Each stage holds A_hi, A_lo, B_hi, B_lo (64 KB); three MMA passes per stage
// (hi*hi, lo*hi, hi*lo) share fragments. NITER=64, 3 stages (192 KB), 1 CTA/SM.
#define BK       64
#define NITER    (HH / BK)            /* 64 */
#define TILE16K  16384
#define STAGE_B  65536
#define NSTAGE   3
#define GEMM_SMEM (NSTAGE * STAGE_B)  /* 196608 */

__device__ __forceinline__ uint32_t sw128(uint32_t off) {
    return off ^ ((off >> 3) & 0x70);
}

__device__ __forceinline__ void ldsm_x4(uint32_t* r, uint32_t addr) {
    asm volatile("ldmatrix.sync.aligned.m8n8.x4.shared.b16 {%0,%1,%2,%3}, [%4];"
                 : "=r"(r[0]), "=r"(r[1]), "=r"(r[2]), "=r"(r[3]) : "r"(addr));
}
__device__ __forceinline__ void mma_bf16(float* c, const uint32_t* a, uint32_t b0, uint32_t b1) {
    asm volatile(
        "mma.sync.aligned.m16n8k16.row.col.f32.bf16.bf16.f32 "
        "{%0,%1,%2,%3}, {%4,%5,%6,%7}, {%8,%9}, {%0,%1,%2,%3};"
        : "+f"(c[0]), "+f"(c[1]), "+f"(c[2]), "+f"(c[3])
        : "r"(a[0]), "r"(a[1]), "r"(a[2]), "r"(a[3]), "r"(b0), "r"(b1));
}
__device__ __forceinline__ void cp16(uint32_t dst, const void* src) {
    asm volatile("cp.async.cg.shared.global [%0], [%1], 16;" :: "r"(dst),
                 "l"((unsigned long long)__cvta_generic_to_global((void*)src)));
}
__device__ __forceinline__ uint32_t smem_u32(const void* p) {
    uint32_t a;
    asm("{ .reg .u64 t; cvta.to.shared.u64 t, %1; cvt.u32.u64 %0, t; }" : "=r"(a) : "l"(p));
    return a;
}

// load A_hi/A_lo (threads 0-127) and B_hi/B_lo (threads 128-255) for one k-chunk
__device__ __forceinline__ void stage_load(uint32_t sbase, int iter, int mtile, int ntile, int tid) {
    int koff = iter * BK;
    int row  = tid & 127;
    bool isB = tid >= 128;
    const __nv_bfloat16* hi = isB
        ? g_whi + (size_t)(ntile * 128 + row) * HH + koff
        : g_xhi + (size_t)(mtile * 128 + row) * HH + koff;
    const __nv_bfloat16* lo = isB
        ? g_wlo + (size_t)(ntile * 128 + row) * HH + koff
        : g_xlo + (size_t)(mtile * 128 + row) * HH + koff;
    uint32_t base = sbase + (isB ? 2 * TILE16K : 0);
#pragma unroll
    for (int c = 0; c < 8; c++) {
        uint32_t off = sw128(row * 128 + c * 16);
        cp16(base + off, hi + c * 8);
        cp16(base + TILE16K + off, lo + c * 8);
    }
}

__global__ void __launch_bounds__(256, 1) gemm_kernel(const float* __restrict__ bias,
                                                      float* __restrict__ out) {
    extern __shared__ char smem[];
    uint32_t sb = smem_u32(smem);
    int tid = threadIdx.x;
    int lane = tid & 31, wid = tid >> 5;
    int wm = wid & 1, wn = wid >> 1;          // warp grid 2 (M) x 4 (N)
    int ntile = blockIdx.x;                   // 32
    int mtile = blockIdx.y;                   // 16

    float acc[4][4][4];
#pragma unroll
    for (int i = 0; i < 4; i++)
#pragma unroll
        for (int j = 0; j < 4; j++)
#pragma unroll
            for (int q = 0; q < 4; q++) acc[i][j][q] = 0.0f;

    // prologue: 2 stages in flight
#pragma unroll
    for (int s = 0; s < NSTAGE - 1; s++) {
        stage_load(sb + s * STAGE_B, s, mtile, ntile, tid);
        asm volatile("cp.async.commit_group;" ::: "memory");
    }

    int arow = (lane & 15);
    int achk = (lane >> 4) * 16;

    int cur = 0, wrt = NSTAGE - 1;
    for (int it = 0; it < NITER; it++) {
        asm volatile("cp.async.wait_group %0;" :: "n"(NSTAGE - 2) : "memory");
        __syncthreads();
        if (it + NSTAGE - 1 < NITER) {
            stage_load(sb + wrt * STAGE_B, it + NSTAGE - 1, mtile, ntile, tid);
        }
        asm volatile("cp.async.commit_group;" ::: "memory");

        uint32_t Ah = sb + cur * STAGE_B;
        uint32_t Al = Ah + TILE16K;
        uint32_t Bh = Ah + 2 * TILE16K;
        uint32_t Bl = Ah + 3 * TILE16K;
#pragma unroll
        for (int ks = 0; ks < 4; ks++) {
            uint32_t ah[4][4], al[4][4];
#pragma unroll
            for (int i = 0; i < 4; i++) {
                int row = wm * 64 + i * 16 + arow;
                uint32_t off = sw128(row * 128 + ks * 32 + achk);
                ldsm_x4(ah[i], Ah + off);
                ldsm_x4(al[i], Al + off);
            }
            uint32_t bh[2][4], bl[2][4];
#pragma unroll
            for (int jj = 0; jj < 2; jj++) {
                int row = wn * 32 + jj * 16 + arow;
                uint32_t off = sw128(row * 128 + ks * 32 + achk);
                ldsm_x4(bh[jj], Bh + off);   // smem holds [n][k]: pairs are k-pairs
                ldsm_x4(bl[jj], Bl + off);
            }
#pragma unroll
            for (int i = 0; i < 4; i++)
#pragma unroll
                for (int j = 0; j < 4; j++) {
                    int jj = j >> 1, p = j & 1;
                    mma_bf16(acc[i][j], ah[i], bh[jj][p], bh[jj][p + 2]);  // hi*hi
                    mma_bf16(acc[i][j], al[i], bh[jj][p], bh[jj][p + 2]);  // lo*hi
                    mma_bf16(acc[i][j], ah[i], bl[jj][p], bl[jj][p + 2]);  // hi*lo
                }
        }
        cur = (cur + 1 < NSTAGE) ? cur + 1 : 0;
        wrt = (wrt + 1 < NSTAGE) ? wrt + 1 : 0;
    }

    // epilogue: add bias, store fp32
#pragma unroll
    for (int i = 0; i < 4; i++) {
#pragma unroll
        for (int j = 0; j < 4; j++) {
            int m = mtile * 128 + wm * 64 + i * 16 + (lane >> 2);
            int n = ntile * 128 + wn * 32 + j * 8 + (lane & 3) * 2;
            float2 bv = *reinterpret_cast<const float2*>(bias + n);
            float2 o0, o1;
            o0.x = acc[i][j][0] + bv.x;
            o0.y = acc[i][j][1] + bv.y;
            o1.x = acc[i][j][2] + bv.x;
            o1.y = acc[i][j][3] + bv.y;
            *reinterpret_cast<float2*>(out + (size_t)m * OO + n) = o0;
            *reinterpret_cast<float2*>(out + (size_t)(m + 8) * OO + n) = o1;
        }
    }
}

// stub symbol
__global__ void ColumnParallelLinearWithLoRA_893353198245_kernel() {}

// ---------------- launch ----------------
extern "C" void kernel_launch(void* const* d_in, const int* in_sizes, int n_in,
                              void* d_out, int out_size) {
    const float* x    = (const float*)d_in[0];
    const float* w    = (const float*)d_in[1];
    const float* bias = (const float*)d_in[2];
    const float* la   = (const float*)d_in[3];
    const float* lb   = (const float*)d_in[4];
    const int*   idx  = (const int*)d_in[5];
    float* out = (float*)d_out;

    cudaFuncSetAttribute(gemm_kernel, cudaFuncAttributeMaxDynamicSharedMemorySize, GEMM_SMEM);

    prep_kernel<<<1, 1024>>>(idx);
    split_x_kernel<<<(TT * HH / 8) / 256, 256>>>(x);
    split_w_kernel<<<(OO * HH / 8) / 256, 256>>>(w);
    shrink_kernel<<<8 * LL, 512>>>(x, la);
    gemm_kernel<<<dim3(32, 16), 256, GEMM_SMEM>>>(bias, out);
    expand_kernel<<<LL * 8, 256>>>(lb, out);
}

// round 7
// speedup vs baseline: 3.6526x; 2.2556x over previous
#include <cuda_runtime.h>
#include <cuda_fp16.h>
#include <cstdint>

#define TT 2048
#define HH 4096
#define OO 4096
#define LL 32
#define RR 16

// ---------------- device scratch (no cudaMalloc allowed) ----------------
__device__ __half g_xh[TT * HH];   // fp16 hi, row-major [T][H]
__device__ __half g_xl[TT * HH];   // fp16 lo (x - hi)
__device__ __half g_wh[OO * HH];   // fp16 W, row-major [O][H]
__device__ int   g_cnt[LL];
__device__ int   g_off[LL];
__device__ int   g_tok[TT];
__device__ float g_shrunk[TT * RR];

// ---------------- prep: zero shrunk, index width detect, group tokens ----------------
__global__ void prep_kernel(const int* __restrict__ w) {
    __shared__ int s_ok;
    __shared__ int s_cnt[LL];
    __shared__ int s_off[LL];
    int tid = threadIdx.x;
    for (int i = tid; i < TT * RR; i += 1024) g_shrunk[i] = 0.0f;
    if (tid == 0) s_ok = 1;
    if (tid < LL) s_cnt[tid] = 0;
    __syncthreads();
    // int64 detection: viewed as int32 pairs (lo,hi), hi must be the sign
    // extension of a valid index in [-1, LL)
    if (tid < 1024) {
        int lo = w[2 * tid], hi = w[2 * tid + 1];
        int expect = (lo < 0) ? -1 : 0;
        if (hi != expect || lo < -1 || lo >= LL) atomicExch(&s_ok, 0);
    }
    __syncthreads();
    int is64 = s_ok;
    for (int t = tid; t < TT; t += 1024) {
        int l = is64 ? w[2 * t] : w[t];
        if (l >= 0) atomicAdd(&s_cnt[l], 1);
    }
    __syncthreads();
    if (tid == 0) {
        int a = 0;
        for (int l = 0; l < LL; l++) { s_off[l] = a; a += s_cnt[l]; }
    }
    __syncthreads();
    if (tid < LL) { g_off[tid] = s_off[tid]; g_cnt[tid] = s_cnt[tid]; }
    if (tid < LL) s_cnt[tid] = 0;
    __syncthreads();
    for (int t = tid; t < TT; t += 1024) {
        int l = is64 ? w[2 * t] : w[t];
        if (l >= 0) {
            int p = atomicAdd(&s_cnt[l], 1);
            g_tok[s_off[l] + p] = t;
        }
    }
}

// ---------------- fp32 -> fp16 hi/lo split (x) and fp16 convert (w) ----------------
__global__ void __launch_bounds__(256) split_x_kernel(const float* __restrict__ x) {
    size_t i = ((size_t)blockIdx.x * 256 + threadIdx.x) * 8;
    float4 v0 = *reinterpret_cast<const float4*>(x + i);
    float4 v1 = *reinterpret_cast<const float4*>(x + i + 4);
    float f[8] = {v0.x, v0.y, v0.z, v0.w, v1.x, v1.y, v1.z, v1.w};
    __align__(16) __half h[8];
    __align__(16) __half l[8];
#pragma unroll
    for (int q = 0; q < 8; q++) {
        h[q] = __float2half_rn(f[q]);
        l[q] = __float2half_rn(f[q] - __half2float(h[q]));
    }
    *reinterpret_cast<uint4*>(g_xh + i) = *reinterpret_cast<uint4*>(h);
    *reinterpret_cast<uint4*>(g_xl + i) = *reinterpret_cast<uint4*>(l);
}

__global__ void __launch_bounds__(256) split_w_kernel(const float* __restrict__ w) {
    size_t i = ((size_t)blockIdx.x * 256 + threadIdx.x) * 8;
    float4 v0 = *reinterpret_cast<const float4*>(w + i);
    float4 v1 = *reinterpret_cast<const float4*>(w + i + 4);
    float f[8] = {v0.x, v0.y, v0.z, v0.w, v1.x, v1.y, v1.z, v1.w};
    __align__(16) __half h[8];
#pragma unroll
    for (int q = 0; q < 8; q++) h[q] = __float2half_rn(f[q]);
    *reinterpret_cast<uint4*>(g_wh + i) = *reinterpret_cast<uint4*>(h);
}

// ---------------- LoRA shrink (fp32): warp-per-token ----------------
#define SCH 512
__global__ void __launch_bounds__(512) shrink_kernel(const float* __restrict__ x,
                                                     const float* __restrict__ lora_a) {
    __shared__ float As[RR * SCH];   // 32 KB
    int l  = blockIdx.x & 31;
    int ch = blockIdx.x >> 5;
    int c0 = ch * SCH;
    int tid = threadIdx.x;
    const float* Ag = lora_a + (size_t)l * RR * HH + c0;
    for (int i = tid; i < RR * SCH / 4; i += 512) {
        int r = i >> 7;
        int c = (i & 127) * 4;
        *reinterpret_cast<float4*>(As + r * SCH + c) =
            *reinterpret_cast<const float4*>(Ag + (size_t)r * HH + c);
    }
    __syncthreads();
    int cnt = g_cnt[l], off = g_off[l];
    int wrp = tid >> 5, lane = tid & 31;
    for (int it = wrp; it < cnt; it += 16) {
        int t = g_tok[off + it];
        const float* xr = x + (size_t)t * HH + c0;
        float xv[16];
#pragma unroll
        for (int j = 0; j < 16; j++) xv[j] = xr[lane + 32 * j];
        float mine = 0.0f;
#pragma unroll
        for (int r = 0; r < RR; r++) {
            float a = 0.0f;
            const float* Ar = As + r * SCH;
#pragma unroll
            for (int j = 0; j < 16; j++) a += xv[j] * Ar[lane + 32 * j];
#pragma unroll
            for (int o = 16; o; o >>= 1) a += __shfl_xor_sync(0xFFFFFFFFu, a, o);
            if (lane == r) mine = a;
        }
        if (lane < RR) atomicAdd(&g_shrunk[t * RR + lane], mine);
    }
}

// ---------------- LoRA expand: out[t,o] += sum_r S[t,r]*B[l,o,r] ----------------
__global__ void __launch_bounds__(256) expand_kernel(const float* __restrict__ lora_b,
                                                     float* __restrict__ out) {
    __shared__ float Bs[512 * 17];
    int l  = blockIdx.x & 31;
    int oc = blockIdx.x >> 5;
    int o0 = oc * 512;
    int tid = threadIdx.x;
    const float* Bg = lora_b + ((size_t)l * OO + o0) * RR;
    for (int i = tid; i < 512 * RR; i += 256) {
        int o = i >> 4, r = i & 15;
        Bs[o * 17 + r] = Bg[i];
    }
    __syncthreads();
    int cnt = g_cnt[l], off = g_off[l];
    for (int it = 0; it < cnt; it++) {
        int t = g_tok[off + it];
        const float* sv = g_shrunk + t * RR;
        float s[RR];
#pragma unroll
        for (int r = 0; r < RR; r++) s[r] = __ldg(sv + r);
#pragma unroll
        for (int u = 0; u < 2; u++) {
            int o = tid + u * 256;
            float acc = 0.0f;
#pragma unroll
            for (int r = 0; r < RR; r++) acc += Bs[o * 17 + r] * s[r];
            out[(size_t)t * OO + o0 + o] += acc;
        }
    }
}

// ---------------- main GEMM: mma.sync fp16, fused 2-pass fp16x2 ----------------
// out = (x_hi + x_lo) . w_fp16 ; stage = {A_hi, A_lo, B} = 48 KB
// 2 stages (96 KB) -> 2 CTAs/SM; one barrier per iter; NITER = 64.
#define BK       64
#define NITER    (HH / BK)            /* 64 */
#define TILE16K  16384
#define STAGE_B  49152
#define NSTAGE   2
#define GEMM_SMEM (NSTAGE * STAGE_B)  /* 98304 */

__device__ __forceinline__ uint32_t sw128(uint32_t off) {
    return off ^ ((off >> 3) & 0x70);
}

__device__ __forceinline__ void ldsm_x4(uint32_t* r, uint32_t addr) {
    asm volatile("ldmatrix.sync.aligned.m8n8.x4.shared.b16 {%0,%1,%2,%3}, [%4];"
                 : "=r"(r[0]), "=r"(r[1]), "=r"(r[2]), "=r"(r[3]) : "r"(addr));
}
__device__ __forceinline__ void mma_f16(float* c, const uint32_t* a, uint32_t b0, uint32_t b1) {
    asm volatile(
        "mma.sync.aligned.m16n8k16.row.col.f32.f16.f16.f32 "
        "{%0,%1,%2,%3}, {%4,%5,%6,%7}, {%8,%9}, {%0,%1,%2,%3};"
        : "+f"(c[0]), "+f"(c[1]), "+f"(c[2]), "+f"(c[3])
        : "r"(a[0]), "r"(a[1]), "r"(a[2]), "r"(a[3]), "r"(b0), "r"(b1));
}
__device__ __forceinline__ void cp16(uint32_t dst, const void* src) {
    asm volatile("cp.async.cg.shared.global [%0], [%1], 16;" :: "r"(dst),
                 "l"((unsigned long long)__cvta_generic_to_global((void*)src)));
}
__device__ __forceinline__ uint32_t smem_u32(const void* p) {
    uint32_t a;
    asm("{ .reg .u64 t; cvta.to.shared.u64 t, %1; cvt.u32.u64 %0, t; }" : "=r"(a) : "l"(p));
    return a;
}

// load A_hi, A_lo, B (3 x 16 KB) for one k-chunk; 3072 x 16B by 256 threads
__device__ __forceinline__ void stage_load(uint32_t sbase, int iter, int mtile, int ntile, int tid) {
    int koff = iter * BK;
#pragma unroll
    for (int q = 0; q < 12; q++) {
        int j = q * 256 + tid;          // 0..3071
        int tile = j >> 10;             // 0:A_hi 1:A_lo 2:B
        int u = j & 1023;
        int row = u >> 3, seg = u & 7;
        const __half* src;
        if (tile == 0)      src = g_xh + (size_t)(mtile * 128 + row) * HH + koff + seg * 8;
        else if (tile == 1) src = g_xl + (size_t)(mtile * 128 + row) * HH + koff + seg * 8;
        else                src = g_wh + (size_t)(ntile * 128 + row) * HH + koff + seg * 8;
        cp16(sbase + tile * TILE16K + sw128(row * 128 + seg * 16), src);
    }
}

__global__ void __launch_bounds__(256, 2) gemm_kernel(const float* __restrict__ bias,
                                                      float* __restrict__ out) {
    extern __shared__ char smem[];
    uint32_t sb = smem_u32(smem);
    int tid = threadIdx.x;
    int lane = tid & 31, wid = tid >> 5;
    int wm = wid & 1, wn = wid >> 1;          // warp grid 2 (M) x 4 (N)
    int ntile = blockIdx.x;                   // 32
    int mtile = blockIdx.y;                   // 16

    float acc[4][4][4];
#pragma unroll
    for (int i = 0; i < 4; i++)
#pragma unroll
        for (int j = 0; j < 4; j++)
#pragma unroll
            for (int q = 0; q < 4; q++) acc[i][j][q] = 0.0f;

    // prologue: stage 0
    stage_load(sb, 0, mtile, ntile, tid);
    asm volatile("cp.async.commit_group;" ::: "memory");

    int arow = (lane & 15);
    int achk = (lane >> 4) * 16;

    for (int it = 0; it < NITER; it++) {
        asm volatile("cp.async.wait_group 0;" ::: "memory");
        __syncthreads();
        // overlap: load next stage while computing current
        if (it + 1 < NITER) {
            stage_load(sb + ((it + 1) & 1) * STAGE_B, it + 1, mtile, ntile, tid);
        }
        asm volatile("cp.async.commit_group;" ::: "memory");

        uint32_t Ah = sb + (it & 1) * STAGE_B;
        uint32_t Al = Ah + TILE16K;
        uint32_t Bb = Ah + 2 * TILE16K;
#pragma unroll
        for (int ks = 0; ks < 4; ks++) {
            uint32_t ah[4][4], al[4][4];
#pragma unroll
            for (int i = 0; i < 4; i++) {
                int row = wm * 64 + i * 16 + arow;
                uint32_t off = sw128(row * 128 + ks * 32 + achk);
                ldsm_x4(ah[i], Ah + off);
                ldsm_x4(al[i], Al + off);
            }
            uint32_t b[2][4];
#pragma unroll
            for (int jj = 0; jj < 2; jj++) {
                int row = wn * 32 + jj * 16 + arow;
                uint32_t off = sw128(row * 128 + ks * 32 + achk);
                ldsm_x4(b[jj], Bb + off);   // smem holds [n][k]: pairs are k-pairs
            }
#pragma unroll
            for (int i = 0; i < 4; i++)
#pragma unroll
                for (int j = 0; j < 4; j++) {
                    int jj = j >> 1, p = j & 1;
                    mma_f16(acc[i][j], ah[i], b[jj][p], b[jj][p + 2]);  // hi * w
                    mma_f16(acc[i][j], al[i], b[jj][p], b[jj][p + 2]);  // lo * w
                }
        }
    }

    // epilogue: add bias, store fp32
#pragma unroll
    for (int i = 0; i < 4; i++) {
#pragma unroll
        for (int j = 0; j < 4; j++) {
            int m = mtile * 128 + wm * 64 + i * 16 + (lane >> 2);
            int n = ntile * 128 + wn * 32 + j * 8 + (lane & 3) * 2;
            float2 bv = *reinterpret_cast<const float2*>(bias + n);
            float2 o0, o1;
            o0.x = acc[i][j][0] + bv.x;
            o0.y = acc[i][j][1] + bv.y;
            o1.x = acc[i][j][2] + bv.x;
            o1.y = acc[i][j][3] + bv.y;
            *reinterpret_cast<float2*>(out + (size_t)m * OO + n) = o0;
            *reinterpret_cast<float2*>(out + (size_t)(m + 8) * OO + n) = o1;
        }
    }
}

// stub symbol
__global__ void ColumnParallelLinearWithLoRA_893353198245_kernel() {}

// ---------------- launch ----------------
extern "C" void kernel_launch(void* const* d_in, const int* in_sizes, int n_in,
                              void* d_out, int out_size) {
    const float* x    = (const float*)d_in[0];
    const float* w    = (const float*)d_in[1];
    const float* bias = (const float*)d_in[2];
    const float* la   = (const float*)d_in[3];
    const float* lb   = (const float*)d_in[4];
    const int*   idx  = (const int*)d_in[5];
    float* out = (float*)d_out;

    cudaFuncSetAttribute(gemm_kernel, cudaFuncAttributeMaxDynamicSharedMemorySize, GEMM_SMEM);

    prep_kernel<<<1, 1024>>>(idx);
    split_x_kernel<<<(TT * HH / 8) / 256, 256>>>(x);
    split_w_kernel<<<(OO * HH / 8) / 256, 256>>>(w);
    shrink_kernel<<<8 * LL, 512>>>(x, la);
    gemm_kernel<<<dim3(32, 16), 256, GEMM_SMEM>>>(bias, out);
    expand_kernel<<<LL * 8, 256>>>(lb, out);
}

// round 8
// speedup vs baseline: 6.0846x; 1.6658x over previous
#include <cuda_runtime.h>
#include <cuda_fp16.h>
#include <cstdint>

#define TT 2048
#define HH 4096
#define OO 4096
#define LL 32
#define RR 16

// ---------------- device scratch (no cudaMalloc allowed) ----------------
__device__ __half g_xh[TT * HH];   // fp16 x, row-major [T][H]
__device__ __half g_wh[OO * HH];   // fp16 W, row-major [O][H]
__device__ int   g_cnt[LL];
__device__ int   g_off[LL];
__device__ int   g_tok[TT];
__device__ float g_shrunk[TT * RR];

// ---------------- prep: zero shrunk, index width detect, group tokens ----------------
__global__ void prep_kernel(const int* __restrict__ w) {
    __shared__ int s_ok;
    __shared__ int s_cnt[LL];
    __shared__ int s_off[LL];
    int tid = threadIdx.x;
    for (int i = tid; i < TT * RR; i += 1024) g_shrunk[i] = 0.0f;
    if (tid == 0) s_ok = 1;
    if (tid < LL) s_cnt[tid] = 0;
    __syncthreads();
    // int64 detection: viewed as int32 pairs (lo,hi), hi must be the sign
    // extension of a valid index in [-1, LL)
    if (tid < 1024) {
        int lo = w[2 * tid], hi = w[2 * tid + 1];
        int expect = (lo < 0) ? -1 : 0;
        if (hi != expect || lo < -1 || lo >= LL) atomicExch(&s_ok, 0);
    }
    __syncthreads();
    int is64 = s_ok;
    for (int t = tid; t < TT; t += 1024) {
        int l = is64 ? w[2 * t] : w[t];
        if (l >= 0) atomicAdd(&s_cnt[l], 1);
    }
    __syncthreads();
    if (tid == 0) {
        int a = 0;
        for (int l = 0; l < LL; l++) { s_off[l] = a; a += s_cnt[l]; }
    }
    __syncthreads();
    if (tid < LL) { g_off[tid] = s_off[tid]; g_cnt[tid] = s_cnt[tid]; }
    if (tid < LL) s_cnt[tid] = 0;
    __syncthreads();
    for (int t = tid; t < TT; t += 1024) {
        int l = is64 ? w[2 * t] : w[t];
        if (l >= 0) {
            int p = atomicAdd(&s_cnt[l], 1);
            g_tok[s_off[l] + p] = t;
        }
    }
}

// ---------------- fp32 -> fp16 convert ----------------
__global__ void __launch_bounds__(256) split_x_kernel(const float* __restrict__ x) {
    size_t i = ((size_t)blockIdx.x * 256 + threadIdx.x) * 8;
    float4 v0 = *reinterpret_cast<const float4*>(x + i);
    float4 v1 = *reinterpret_cast<const float4*>(x + i + 4);
    float f[8] = {v0.x, v0.y, v0.z, v0.w, v1.x, v1.y, v1.z, v1.w};
    __align__(16) __half h[8];
#pragma unroll
    for (int q = 0; q < 8; q++) h[q] = __float2half_rn(f[q]);
    *reinterpret_cast<uint4*>(g_xh + i) = *reinterpret_cast<uint4*>(h);
}

__global__ void __launch_bounds__(256) split_w_kernel(const float* __restrict__ w) {
    size_t i = ((size_t)blockIdx.x * 256 + threadIdx.x) * 8;
    float4 v0 = *reinterpret_cast<const float4*>(w + i);
    float4 v1 = *reinterpret_cast<const float4*>(w + i + 4);
    float f[8] = {v0.x, v0.y, v0.z, v0.w, v1.x, v1.y, v1.z, v1.w};
    __align__(16) __half h[8];
#pragma unroll
    for (int q = 0; q < 8; q++) h[q] = __float2half_rn(f[q]);
    *reinterpret_cast<uint4*>(g_wh + i) = *reinterpret_cast<uint4*>(h);
}

// ---------------- LoRA shrink (fp32): warp-per-token ----------------
#define SCH 512
__global__ void __launch_bounds__(512) shrink_kernel(const float* __restrict__ x,
                                                     const float* __restrict__ lora_a) {
    __shared__ float As[RR * SCH];   // 32 KB
    int l  = blockIdx.x & 31;
    int ch = blockIdx.x >> 5;
    int c0 = ch * SCH;
    int tid = threadIdx.x;
    const float* Ag = lora_a + (size_t)l * RR * HH + c0;
    for (int i = tid; i < RR * SCH / 4; i += 512) {
        int r = i >> 7;
        int c = (i & 127) * 4;
        *reinterpret_cast<float4*>(As + r * SCH + c) =
            *reinterpret_cast<const float4*>(Ag + (size_t)r * HH + c);
    }
    __syncthreads();
    int cnt = g_cnt[l], off = g_off[l];
    int wrp = tid >> 5, lane = tid & 31;
    for (int it = wrp; it < cnt; it += 16) {
        int t = g_tok[off + it];
        const float* xr = x + (size_t)t * HH + c0;
        float xv[16];
#pragma unroll
        for (int j = 0; j < 16; j++) xv[j] = xr[lane + 32 * j];
        float mine = 0.0f;
#pragma unroll
        for (int r = 0; r < RR; r++) {
            float a = 0.0f;
            const float* Ar = As + r * SCH;
#pragma unroll
            for (int j = 0; j < 16; j++) a += xv[j] * Ar[lane + 32 * j];
#pragma unroll
            for (int o = 16; o; o >>= 1) a += __shfl_xor_sync(0xFFFFFFFFu, a, o);
            if (lane == r) mine = a;
        }
        if (lane < RR) atomicAdd(&g_shrunk[t * RR + lane], mine);
    }
}

// ---------------- LoRA expand: out[t,o] += sum_r S[t,r]*B[l,o,r] ----------------
__global__ void __launch_bounds__(256) expand_kernel(const float* __restrict__ lora_b,
                                                     float* __restrict__ out) {
    __shared__ float Bs[512 * 17];
    int l  = blockIdx.x & 31;
    int oc = blockIdx.x >> 5;
    int o0 = oc * 512;
    int tid = threadIdx.x;
    const float* Bg = lora_b + ((size_t)l * OO + o0) * RR;
    for (int i = tid; i < 512 * RR; i += 256) {
        int o = i >> 4, r = i & 15;
        Bs[o * 17 + r] = Bg[i];
    }
    __syncthreads();
    int cnt = g_cnt[l], off = g_off[l];
    for (int it = 0; it < cnt; it++) {
        int t = g_tok[off + it];
        const float* sv = g_shrunk + t * RR;
        float s[RR];
#pragma unroll
        for (int r = 0; r < RR; r++) s[r] = __ldg(sv + r);
#pragma unroll
        for (int u = 0; u < 2; u++) {
            int o = tid + u * 256;
            float acc = 0.0f;
#pragma unroll
            for (int r = 0; r < RR; r++) acc += Bs[o * 17 + r] * s[r];
            out[(size_t)t * OO + o0 + o] += acc;
        }
    }
}

// ---------------- main GEMM: mma.sync fp16, single pass ----------------
// out = x_fp16 . w_fp16 (fp32 accum); stage = {A, B} = 32 KB
// 3 stages (96 KB) -> 2 CTAs/SM; wait_group 1 gives one full iter of slack.
#define BK       64
#define NITER    (HH / BK)            /* 64 */
#define TILE16K  16384
#define STAGE_B  32768
#define NSTAGE   3
#define GEMM_SMEM (NSTAGE * STAGE_B)  /* 98304 */

__device__ __forceinline__ uint32_t sw128(uint32_t off) {
    return off ^ ((off >> 3) & 0x70);
}

__device__ __forceinline__ void ldsm_x4(uint32_t* r, uint32_t addr) {
    asm volatile("ldmatrix.sync.aligned.m8n8.x4.shared.b16 {%0,%1,%2,%3}, [%4];"
                 : "=r"(r[0]), "=r"(r[1]), "=r"(r[2]), "=r"(r[3]) : "r"(addr));
}
__device__ __forceinline__ void mma_f16(float* c, const uint32_t* a, uint32_t b0, uint32_t b1) {
    asm volatile(
        "mma.sync.aligned.m16n8k16.row.col.f32.f16.f16.f32 "
        "{%0,%1,%2,%3}, {%4,%5,%6,%7}, {%8,%9}, {%0,%1,%2,%3};"
        : "+f"(c[0]), "+f"(c[1]), "+f"(c[2]), "+f"(c[3])
        : "r"(a[0]), "r"(a[1]), "r"(a[2]), "r"(a[3]), "r"(b0), "r"(b1));
}
__device__ __forceinline__ void cp16(uint32_t dst, const void* src) {
    asm volatile("cp.async.cg.shared.global [%0], [%1], 16;" :: "r"(dst),
                 "l"((unsigned long long)__cvta_generic_to_global((void*)src)));
}
__device__ __forceinline__ uint32_t smem_u32(const void* p) {
    uint32_t a;
    asm("{ .reg .u64 t; cvta.to.shared.u64 t, %1; cvt.u32.u64 %0, t; }" : "=r"(a) : "l"(p));
    return a;
}

// load A, B (2 x 16 KB) for one k-chunk; 2048 x 16B by 256 threads
__device__ __forceinline__ void stage_load(uint32_t sbase, int iter, int mtile, int ntile, int tid) {
    int koff = iter * BK;
#pragma unroll
    for (int q = 0; q < 8; q++) {
        int j = q * 256 + tid;          // 0..2047
        int tile = j >> 10;             // 0:A 1:B
        int u = j & 1023;
        int row = u >> 3, seg = u & 7;
        const __half* src = tile
            ? g_wh + (size_t)(ntile * 128 + row) * HH + koff + seg * 8
            : g_xh + (size_t)(mtile * 128 + row) * HH + koff + seg * 8;
        cp16(sbase + tile * TILE16K + sw128(row * 128 + seg * 16), src);
    }
}

__global__ void __launch_bounds__(256, 2) gemm_kernel(const float* __restrict__ bias,
                                                      float* __restrict__ out) {
    extern __shared__ char smem[];
    uint32_t sb = smem_u32(smem);
    int tid = threadIdx.x;
    int lane = tid & 31, wid = tid >> 5;
    int wm = wid & 1, wn = wid >> 1;          // warp grid 2 (M) x 4 (N)
    int ntile = blockIdx.x;                   // 32
    int mtile = blockIdx.y;                   // 16

    float acc[4][4][4];
#pragma unroll
    for (int i = 0; i < 4; i++)
#pragma unroll
        for (int j = 0; j < 4; j++)
#pragma unroll
            for (int q = 0; q < 4; q++) acc[i][j][q] = 0.0f;

    // prologue: 2 stages in flight
#pragma unroll
    for (int s = 0; s < NSTAGE - 1; s++) {
        stage_load(sb + s * STAGE_B, s, mtile, ntile, tid);
        asm volatile("cp.async.commit_group;" ::: "memory");
    }

    int arow = (lane & 15);
    int achk = (lane >> 4) * 16;

    int cur = 0, wrt = NSTAGE - 1;
    for (int it = 0; it < NITER; it++) {
        asm volatile("cp.async.wait_group 1;" ::: "memory");
        __syncthreads();
        // load stage it+2 into buffer consumed in iter it-1
        if (it + NSTAGE - 1 < NITER) {
            stage_load(sb + wrt * STAGE_B, it + NSTAGE - 1, mtile, ntile, tid);
        }
        asm volatile("cp.async.commit_group;" ::: "memory");

        uint32_t Ab = sb + cur * STAGE_B;
        uint32_t Bb = Ab + TILE16K;
#pragma unroll
        for (int ks = 0; ks < 4; ks++) {
            uint32_t a[4][4];
#pragma unroll
            for (int i = 0; i < 4; i++) {
                int row = wm * 64 + i * 16 + arow;
                uint32_t off = sw128(row * 128 + ks * 32 + achk);
                ldsm_x4(a[i], Ab + off);
            }
            uint32_t b[2][4];
#pragma unroll
            for (int jj = 0; jj < 2; jj++) {
                int row = wn * 32 + jj * 16 + arow;
                uint32_t off = sw128(row * 128 + ks * 32 + achk);
                ldsm_x4(b[jj], Bb + off);   // smem holds [n][k]: pairs are k-pairs
            }
#pragma unroll
            for (int i = 0; i < 4; i++)
#pragma unroll
                for (int j = 0; j < 4; j++) {
                    int jj = j >> 1, p = j & 1;
                    mma_f16(acc[i][j], a[i], b[jj][p], b[jj][p + 2]);
                }
        }
        cur = (cur + 1 < NSTAGE) ? cur + 1 : 0;
        wrt = (wrt + 1 < NSTAGE) ? wrt + 1 : 0;
    }

    // epilogue: add bias, store fp32
#pragma unroll
    for (int i = 0; i < 4; i++) {
#pragma unroll
        for (int j = 0; j < 4; j++) {
            int m = mtile * 128 + wm * 64 + i * 16 + (lane >> 2);
            int n = ntile * 128 + wn * 32 + j * 8 + (lane & 3) * 2;
            float2 bv = *reinterpret_cast<const float2*>(bias + n);
            float2 o0, o1;
            o0.x = acc[i][j][0] + bv.x;
            o0.y = acc[i][j][1] + bv.y;
            o1.x = acc[i][j][2] + bv.x;
            o1.y = acc[i][j][3] + bv.y;
            *reinterpret_cast<float2*>(out + (size_t)m * OO + n) = o0;
            *reinterpret_cast<float2*>(out + (size_t)(m + 8) * OO + n) = o1;
        }
    }
}

// stub symbol
__global__ void ColumnParallelLinearWithLoRA_893353198245_kernel() {}

// ---------------- launch ----------------
extern "C" void kernel_launch(void* const* d_in, const int* in_sizes, int n_in,
                              void* d_out, int out_size) {
    const float* x    = (const float*)d_in[0];
    const float* w    = (const float*)d_in[1];
    const float* bias = (const float*)d_in[2];
    const float* la   = (const float*)d_in[3];
    const float* lb   = (const float*)d_in[4];
    const int*   idx  = (const int*)d_in[5];
    float* out = (float*)d_out;

    cudaFuncSetAttribute(gemm_kernel, cudaFuncAttributeMaxDynamicSharedMemorySize, GEMM_SMEM);

    prep_kernel<<<1, 1024>>>(idx);
    split_x_kernel<<<(TT * HH / 8) / 256, 256>>>(x);
    split_w_kernel<<<(OO * HH / 8) / 256, 256>>>(w);
    shrink_kernel<<<8 * LL, 512>>>(x, la);
    gemm_kernel<<<dim3(32, 16), 256, GEMM_SMEM>>>(bias, out);
    expand_kernel<<<LL * 8, 256>>>(lb, out);
}

// round 11
// speedup vs baseline: 6.3679x; 1.0466x over previous
#include <cuda_runtime.h>
#include <cuda_fp16.h>
#include <cstdint>

#define TT 2048
#define HH 4096
#define OO 4096
#define LL 32
#define RR 16

// ---------------- device scratch (no cudaMalloc allowed) ----------------
__device__ __half g_xh[TT * HH];   // fp16 x, row-major [T][H]
__device__ __half g_wh[OO * HH];   // fp16 W, row-major [O][H]
__device__ int   g_cnt[LL];
__device__ int   g_off[LL];
__device__ int   g_tok[TT];
__device__ float g_shrunk[TT * RR];

// ---------------- helpers ----------------
__device__ __forceinline__ uint32_t sw128(uint32_t off) {
    return off ^ ((off >> 3) & 0x70);
}
__device__ __forceinline__ void ldsm_x4(uint32_t* r, uint32_t addr) {
    asm volatile("ldmatrix.sync.aligned.m8n8.x4.shared.b16 {%0,%1,%2,%3}, [%4];"
                 : "=r"(r[0]), "=r"(r[1]), "=r"(r[2]), "=r"(r[3]) : "r"(addr));
}
__device__ __forceinline__ void mma_f16(float* c, const uint32_t* a, uint32_t b0, uint32_t b1) {
    asm volatile(
        "mma.sync.aligned.m16n8k16.row.col.f32.f16.f16.f32 "
        "{%0,%1,%2,%3}, {%4,%5,%6,%7}, {%8,%9}, {%0,%1,%2,%3};"
        : "+f"(c[0]), "+f"(c[1]), "+f"(c[2]), "+f"(c[3])
        : "r"(a[0]), "r"(a[1]), "r"(a[2]), "r"(a[3]), "r"(b0), "r"(b1));
}
__device__ __forceinline__ void cp16(uint32_t dst, const void* src) {
    asm volatile("cp.async.cg.shared.global [%0], [%1], 16;" :: "r"(dst),
                 "l"((unsigned long long)__cvta_generic_to_global((void*)src)));
}
__device__ __forceinline__ uint32_t smem_u32(const void* p) {
    uint32_t a;
    asm("{ .reg .u64 t; cvta.to.shared.u64 t, %1; cvt.u32.u64 %0, t; }" : "=r"(a) : "l"(p));
    return a;
}

// ---------------- pre: splits + prep fused ----------------
// grid = 12289 x 256: blocks 0..4095 split x, 4096..12287 split w, 12288 prep.
#define XBLKS (TT * HH / 8 / 256)    /* 4096 */
#define WBLKS (OO * HH / 8 / 256)    /* 8192 */

__global__ void __launch_bounds__(256) pre_kernel(const float* __restrict__ x,
                                                  const float* __restrict__ w,
                                                  const int* __restrict__ idx) {
    int bid = blockIdx.x;
    int tid = threadIdx.x;
    if (bid < XBLKS + WBLKS) {
        const float* src = (bid < XBLKS) ? x : w;
        __half* dst = (bid < XBLKS) ? g_xh : g_wh;
        size_t i = ((size_t)(bid < XBLKS ? bid : bid - XBLKS) * 256 + tid) * 8;
        float4 v0 = *reinterpret_cast<const float4*>(src + i);
        float4 v1 = *reinterpret_cast<const float4*>(src + i + 4);
        float f[8] = {v0.x, v0.y, v0.z, v0.w, v1.x, v1.y, v1.z, v1.w};
        __align__(16) __half h[8];
#pragma unroll
        for (int q = 0; q < 8; q++) h[q] = __float2half_rn(f[q]);
        *reinterpret_cast<uint4*>(dst + i) = *reinterpret_cast<uint4*>(h);
        return;
    }
    // ---- prep (block 12288, 256 threads) ----
    __shared__ int s_ok;
    __shared__ int s_cnt[LL];
    __shared__ int s_off[LL];
    for (int i = tid; i < TT * RR; i += 256) g_shrunk[i] = 0.0f;
    if (tid == 0) s_ok = 1;
    if (tid < LL) s_cnt[tid] = 0;
    __syncthreads();
    // int64 detection: as int32 pairs (lo,hi), hi must sign-extend an index in [-1, LL)
    for (int t = tid; t < 1024; t += 256) {
        int lo = idx[2 * t], hi = idx[2 * t + 1];
        int expect = (lo < 0) ? -1 : 0;
        if (hi != expect || lo < -1 || lo >= LL) atomicExch(&s_ok, 0);
    }
    __syncthreads();
    int is64 = s_ok;
    for (int t = tid; t < TT; t += 256) {
        int l = is64 ? idx[2 * t] : idx[t];
        if (l >= 0) atomicAdd(&s_cnt[l], 1);
    }
    __syncthreads();
    if (tid == 0) {
        int a = 0;
        for (int l = 0; l < LL; l++) { s_off[l] = a; a += s_cnt[l]; }
    }
    __syncthreads();
    if (tid < LL) { g_off[tid] = s_off[tid]; g_cnt[tid] = s_cnt[tid]; }
    if (tid < LL) s_cnt[tid] = 0;
    __syncthreads();
    for (int t = tid; t < TT; t += 256) {
        int l = is64 ? idx[2 * t] : idx[t];
        if (l >= 0) {
            int p = atomicAdd(&s_cnt[l], 1);
            g_tok[s_off[l] + p] = t;
        }
    }
}

// ---------------- main: shrink blocks + GEMM blocks in one grid ----------------
// blocks 0..255: shrink (adapter l = bid&31, H-chunk = bid>>5, 8 warps)
// blocks 256..767: GEMM tile (g = bid-256; ntile = g&31, mtile = g>>5)
#define SHRBLKS 256
#define SCH 512
#define BK       64
#define NITER    (HH / BK)            /* 64 */
#define TILE16K  16384
#define STAGE_B  32768
#define NSTAGE   3
#define GEMM_SMEM (NSTAGE * STAGE_B)  /* 98304 */

__global__ void __launch_bounds__(256, 2) main_kernel(const float* __restrict__ x,
                                                      const float* __restrict__ lora_a,
                                                      const float* __restrict__ bias,
                                                      float* __restrict__ out) {
    extern __shared__ char smem[];
    int bid = blockIdx.x;
    int tid = threadIdx.x;

    if (bid < SHRBLKS) {
        // ---- LoRA shrink: S[t,r] += x[t,chunk] . A[l,r,chunk] ----
        float* As = reinterpret_cast<float*>(smem);   // RR*SCH = 32 KB of dynamic smem
        int l  = bid & 31;
        int ch = bid >> 5;
        int c0 = ch * SCH;
        const float* Ag = lora_a + (size_t)l * RR * HH + c0;
        for (int i = tid; i < RR * SCH / 4; i += 256) {
            int r = i >> 7;
            int c = (i & 127) * 4;
            *reinterpret_cast<float4*>(As + r * SCH + c) =
                *reinterpret_cast<const float4*>(Ag + (size_t)r * HH + c);
        }
        __syncthreads();
        int cnt = g_cnt[l], off = g_off[l];
        int wrp = tid >> 5, lane = tid & 31;
        for (int it = wrp; it < cnt; it += 8) {
            int t = g_tok[off + it];
            const float* xr = x + (size_t)t * HH + c0;
            float xv[16];
#pragma unroll
            for (int j = 0; j < 16; j++) xv[j] = xr[lane + 32 * j];
            float mine = 0.0f;
#pragma unroll
            for (int r = 0; r < RR; r++) {
                float a = 0.0f;
                const float* Ar = As + r * SCH;
#pragma unroll
                for (int j = 0; j < 16; j++) a += xv[j] * Ar[lane + 32 * j];
#pragma unroll
                for (int o = 16; o; o >>= 1) a += __shfl_xor_sync(0xFFFFFFFFu, a, o);
                if (lane == r) mine = a;
            }
            if (lane < RR) atomicAdd(&g_shrunk[t * RR + lane], mine);
        }
        return;
    }

    // ---- GEMM tile ----
    uint32_t sb = smem_u32(smem);
    int g = bid - SHRBLKS;
    int ntile = g & 31;
    int mtile = g >> 5;
    int lane = tid & 31, wid = tid >> 5;
    int wm = wid & 1, wn = wid >> 1;          // warp grid 2 (M) x 4 (N)

    float acc[4][4][4];
#pragma unroll
    for (int i = 0; i < 4; i++)
#pragma unroll
        for (int j = 0; j < 4; j++)
#pragma unroll
            for (int q = 0; q < 4; q++) acc[i][j][q] = 0.0f;

    // stage loader (lambda-free): defined inline below via macro-ish loop
    auto stage_load = [&](uint32_t sbase, int iter) {
        int koff = iter * BK;
#pragma unroll
        for (int q = 0; q < 8; q++) {
            int j = q * 256 + tid;          // 0..2047
            int tile = j >> 10;             // 0:A 1:B
            int u = j & 1023;
            int row = u >> 3, seg = u & 7;
            const __half* src = tile
                ? g_wh + (size_t)(ntile * 128 + row) * HH + koff + seg * 8
                : g_xh + (size_t)(mtile * 128 + row) * HH + koff + seg * 8;
            cp16(sbase + tile * TILE16K + sw128(row * 128 + seg * 16), src);
        }
    };

    // prologue: 2 stages in flight
#pragma unroll
    for (int s = 0; s < NSTAGE - 1; s++) {
        stage_load(sb + s * STAGE_B, s);
        asm volatile("cp.async.commit_group;" ::: "memory");
    }

    int arow = (lane & 15);
    int achk = (lane >> 4) * 16;

    int cur = 0, wrt = NSTAGE - 1;
    for (int it = 0; it < NITER; it++) {
        asm volatile("cp.async.wait_group 1;" ::: "memory");
        __syncthreads();
        if (it + NSTAGE - 1 < NITER) {
            stage_load(sb + wrt * STAGE_B, it + NSTAGE - 1);
        }
        asm volatile("cp.async.commit_group;" ::: "memory");

        uint32_t Ab = sb + cur * STAGE_B;
        uint32_t Bb = Ab + TILE16K;
#pragma unroll
        for (int ks = 0; ks < 4; ks++) {
            uint32_t a[4][4];
#pragma unroll
            for (int i = 0; i < 4; i++) {
                int row = wm * 64 + i * 16 + arow;
                uint32_t off = sw128(row * 128 + ks * 32 + achk);
                ldsm_x4(a[i], Ab + off);
            }
            uint32_t b[2][4];
#pragma unroll
            for (int jj = 0; jj < 2; jj++) {
                int row = wn * 32 + jj * 16 + arow;
                uint32_t off = sw128(row * 128 + ks * 32 + achk);
                ldsm_x4(b[jj], Bb + off);   // smem holds [n][k]: pairs are k-pairs
            }
#pragma unroll
            for (int i = 0; i < 4; i++)
#pragma unroll
                for (int j = 0; j < 4; j++) {
                    int jj = j >> 1, p = j & 1;
                    mma_f16(acc[i][j], a[i], b[jj][p], b[jj][p + 2]);
                }
        }
        cur = (cur + 1 < NSTAGE) ? cur + 1 : 0;
        wrt = (wrt + 1 < NSTAGE) ? wrt + 1 : 0;
    }

    // epilogue: add bias, store fp32
#pragma unroll
    for (int i = 0; i < 4; i++) {
#pragma unroll
        for (int j = 0; j < 4; j++) {
            int m = mtile * 128 + wm * 64 + i * 16 + (lane >> 2);
            int n = ntile * 128 + wn * 32 + j * 8 + (lane & 3) * 2;
            float2 bv = *reinterpret_cast<const float2*>(bias + n);
            float2 o0, o1;
            o0.x = acc[i][j][0] + bv.x;
            o0.y = acc[i][j][1] + bv.y;
            o1.x = acc[i][j][2] + bv.x;
            o1.y = acc[i][j][3] + bv.y;
            *reinterpret_cast<float2*>(out + (size_t)m * OO + n) = o0;
            *reinterpret_cast<float2*>(out + (size_t)(m + 8) * OO + n) = o1;
        }
    }
}

// ---------------- LoRA expand: out[t,o] += sum_r S[t,r]*B[l,o,r] ----------------
__global__ void __launch_bounds__(256) expand_kernel(const float* __restrict__ lora_b,
                                                     float* __restrict__ out) {
    __shared__ float Bs[512 * 17];
    int l  = blockIdx.x & 31;
    int oc = blockIdx.x >> 5;
    int o0 = oc * 512;
    int tid = threadIdx.x;
    const float* Bg = lora_b + ((size_t)l * OO + o0) * RR;
    for (int i = tid; i < 512 * RR; i += 256) {
        int o = i >> 4, r = i & 15;
        Bs[o * 17 + r] = Bg[i];
    }
    __syncthreads();
    int cnt = g_cnt[l], off = g_off[l];
    for (int it = 0; it < cnt; it++) {
        int t = g_tok[off + it];
        const float* sv = g_shrunk + t * RR;
        float s[RR];
#pragma unroll
        for (int r = 0; r < RR; r++) s[r] = __ldg(sv + r);
#pragma unroll
        for (int u = 0; u < 2; u++) {
            int o = tid + u * 256;
            float acc = 0.0f;
#pragma unroll
            for (int r = 0; r < RR; r++) acc += Bs[o * 17 + r] * s[r];
            out[(size_t)t * OO + o0 + o] += acc;
        }
    }
}

// stub symbol
__global__ void ColumnParallelLinearWithLoRA_893353198245_kernel() {}

// ---------------- launch ----------------
extern "C" void kernel_launch(void* const* d_in, const int* in_sizes, int n_in,
                              void* d_out, int out_size) {
    const float* x    = (const float*)d_in[0];
    const float* w    = (const float*)d_in[1];
    const float* bias = (const float*)d_in[2];
    const float* la   = (const float*)d_in[3];
    const float* lb   = (const float*)d_in[4];
    const int*   idx  = (const int*)d_in[5];
    float* out = (float*)d_out;

    cudaFuncSetAttribute(main_kernel, cudaFuncAttributeMaxDynamicSharedMemorySize, GEMM_SMEM);

    pre_kernel<<<XBLKS + WBLKS + 1, 256>>>(x, w, idx);
    main_kernel<<<SHRBLKS + 512, 256, GEMM_SMEM>>>(x, la, bias, out);
    expand_kernel<<<LL * 8, 256>>>(lb, out);
}